// round 2
// baseline (speedup 1.0000x reference)
#include <cuda_runtime.h>

// VQ-VAE time-series forward, fully fused, fp32.
// B=16384, T*D=512, HID=128, N_TOKENS=8, CODE_DIM=64, N_CODES=512.
// One CTA processes M=64 batch rows end-to-end.
// R2: fp64-accumulated c2 + tree-summed dot for the VQ argmin (kills the
//     near-tie flip seen in R1); z2 dropped (constant across codes).

namespace {
constexpr int kB       = 16384;
constexpr int kM       = 64;
constexpr int kThreads = 512;
constexpr int kTD      = 512;   // T*D == N_TOKENS*CODE_DIM
constexpr int kHid     = 128;
constexpr int kCDim    = 64;
constexpr int kTok     = 8;
// smem: sZ[64][512] | sH[64][128] | sW[128][128] | sC2[256]
constexpr int kSmemFloats = kM * kTD + kM * kHid + 128 * 128 + 256;   // 57600
constexpr int kSmemBytes  = kSmemFloats * 4;                          // 230400 <= 232448
}

// C[64,128-chunk] += A[64,128] * B[128,128], 4x4 register micro-tile.
// r0 = (tid>>5)*4  (warp-uniform -> A loads broadcast), c0 = (tid&31)*4.
__device__ __forceinline__ void gemm128(const float* __restrict__ sA, int lda,
                                        const float* __restrict__ sB,
                                        int r0, int c0, float (&acc)[4][4])
{
  #pragma unroll 4
  for (int kk = 0; kk < 128; kk += 4) {
    float4 av[4], bv[4];
    #pragma unroll
    for (int i = 0; i < 4; ++i)
      av[i] = *reinterpret_cast<const float4*>(sA + (r0 + i) * lda + kk);
    #pragma unroll
    for (int j = 0; j < 4; ++j)
      bv[j] = *reinterpret_cast<const float4*>(sB + (kk + j) * 128 + c0);
    #pragma unroll
    for (int i = 0; i < 4; ++i) {
      acc[i][0] = fmaf(av[i].x, bv[0].x, acc[i][0]);
      acc[i][1] = fmaf(av[i].x, bv[0].y, acc[i][1]);
      acc[i][2] = fmaf(av[i].x, bv[0].z, acc[i][2]);
      acc[i][3] = fmaf(av[i].x, bv[0].w, acc[i][3]);
      acc[i][0] = fmaf(av[i].y, bv[1].x, acc[i][0]);
      acc[i][1] = fmaf(av[i].y, bv[1].y, acc[i][1]);
      acc[i][2] = fmaf(av[i].y, bv[1].z, acc[i][2]);
      acc[i][3] = fmaf(av[i].y, bv[1].w, acc[i][3]);
      acc[i][0] = fmaf(av[i].z, bv[2].x, acc[i][0]);
      acc[i][1] = fmaf(av[i].z, bv[2].y, acc[i][1]);
      acc[i][2] = fmaf(av[i].z, bv[2].z, acc[i][2]);
      acc[i][3] = fmaf(av[i].z, bv[2].w, acc[i][3]);
      acc[i][0] = fmaf(av[i].w, bv[3].x, acc[i][0]);
      acc[i][1] = fmaf(av[i].w, bv[3].y, acc[i][1]);
      acc[i][2] = fmaf(av[i].w, bv[3].z, acc[i][2]);
      acc[i][3] = fmaf(av[i].w, bv[3].w, acc[i][3]);
    }
  }
}

__global__ void __launch_bounds__(kThreads, 1)
vqvae_fused(const float* __restrict__ x,
            const float* __restrict__ ew1, const float* __restrict__ eb1,
            const float* __restrict__ ew2, const float* __restrict__ eb2,
            const float* __restrict__ cbk,
            const float* __restrict__ dw1, const float* __restrict__ db1,
            const float* __restrict__ dw2, const float* __restrict__ db2,
            float* __restrict__ out, long long out_size)
{
  extern __shared__ float smem[];
  float* sZ  = smem;                    // [64][512] x tile, then z_e, then z_q
  float* sH  = sZ + kM * kTD;           // [64][128]
  float* sW  = sH + kM * kHid;          // [128][128] weight / codebook tile
  float* sC2 = sW + 128 * 128;          // [256] per-code ||c||^2 (fp64-accumulated)

  const int tid = threadIdx.x;
  const int b0  = blockIdx.x * kM;
  const int r0  = (tid >> 5) * 4;       // warp-uniform row group
  const int c0  = (tid & 31) * 4;       // per-lane col group

  // ---------------- load X tile [64,512] into sZ ----------------
  {
    const float4* src = reinterpret_cast<const float4*>(x + (size_t)b0 * kTD);
    float4* dst = reinterpret_cast<float4*>(sZ);
    #pragma unroll
    for (int i = 0; i < 16; ++i)
      dst[tid + i * kThreads] = src[tid + i * kThreads];
  }

  float acc[4][4];

  // ---------------- GEMM1: h = relu(X @ enc_w1 + b1) ----------------
  #pragma unroll
  for (int i = 0; i < 4; ++i)
    #pragma unroll
    for (int j = 0; j < 4; ++j) acc[i][j] = 0.f;

  for (int kt = 0; kt < 4; ++kt) {
    __syncthreads();
    const float4* src = reinterpret_cast<const float4*>(ew1 + kt * 128 * kHid);
    float4* dst = reinterpret_cast<float4*>(sW);
    #pragma unroll
    for (int i = 0; i < 8; ++i)
      dst[tid + i * kThreads] = src[tid + i * kThreads];
    __syncthreads();
    gemm128(sZ + kt * 128, kTD, sW, r0, c0, acc);
  }
  #pragma unroll
  for (int i = 0; i < 4; ++i)
    #pragma unroll
    for (int j = 0; j < 4; ++j) {
      float v = acc[i][j] + __ldg(&eb1[c0 + j]);
      sH[(r0 + i) * kHid + c0 + j] = fmaxf(v, 0.f);
    }

  // ---------------- GEMM2: z_e = h @ enc_w2 + b2 (4 N-chunks of 128) ----------------
  for (int nc = 0; nc < 4; ++nc) {
    const int n0 = nc * 128;
    __syncthreads();
    #pragma unroll
    for (int q = tid; q < 4096; q += kThreads) {   // float4 units of the tile
      const int k = q >> 5, j4 = q & 31;
      reinterpret_cast<float4*>(sW)[q] =
          *reinterpret_cast<const float4*>(ew2 + k * kTD + n0 + j4 * 4);
    }
    __syncthreads();
    #pragma unroll
    for (int i = 0; i < 4; ++i)
      #pragma unroll
      for (int j = 0; j < 4; ++j) acc[i][j] = 0.f;
    gemm128(sH, kHid, sW, r0, c0, acc);
    #pragma unroll
    for (int i = 0; i < 4; ++i)
      #pragma unroll
      for (int j = 0; j < 4; ++j)
        sZ[(r0 + i) * kTD + n0 + c0 + j] = acc[i][j] + __ldg(&eb2[n0 + c0 + j]);
  }
  __syncthreads();

  // ---------------- LayerNorm + VQ: one token-instance per thread ----------------
  const int row = tid >> 3;
  const int tok = tid & 7;
  float* zp = sZ + row * kTD + tok * kCDim;

  float4 zf[16];
  float mu = 0.f;
  #pragma unroll
  for (int j = 0; j < 16; ++j) {
    zf[j] = reinterpret_cast<const float4*>(zp)[j];
    mu += (zf[j].x + zf[j].y) + (zf[j].z + zf[j].w);
  }
  mu *= (1.f / 64.f);
  float var = 0.f;
  #pragma unroll
  for (int j = 0; j < 16; ++j) {
    float dx = zf[j].x - mu, dy = zf[j].y - mu, dz = zf[j].z - mu, dw = zf[j].w - mu;
    var += (dx * dx + dy * dy) + (dz * dz + dw * dw);
  }
  var *= (1.f / 64.f);
  const float rs = rsqrtf(var + 1e-5f);
  #pragma unroll
  for (int j = 0; j < 16; ++j) {
    zf[j].x = (zf[j].x - mu) * rs;
    zf[j].y = (zf[j].y - mu) * rs;
    zf[j].z = (zf[j].z - mu) * rs;
    zf[j].w = (zf[j].w - mu) * rs;
  }

  // argmin over codes of  c2[k] - 2*dot[k]   (z2 is constant -> dropped)
  float best = 3.402823466e38f;
  int bidx = 0;
  for (int pass = 0; pass < 2; ++pass) {
    __syncthreads();
    {  // codebook tile: 256 codes x 64 -> sW (contiguous 64KB)
      const float4* src = reinterpret_cast<const float4*>(cbk + pass * 256 * kCDim);
      float4* dst = reinterpret_cast<float4*>(sW);
      #pragma unroll
      for (int i = 0; i < 8; ++i)
        dst[tid + i * kThreads] = src[tid + i * kThreads];
    }
    __syncthreads();
    if (tid < 256) {
      // fp64-accumulated ||c||^2: error ~ ulp(64)/2 ~= 4e-6 instead of ~2e-5
      double s = 0.0;
      const float4* cr = reinterpret_cast<const float4*>(sW + tid * kCDim);
      #pragma unroll
      for (int j = 0; j < 16; ++j) {
        float4 v = cr[j];
        s += (double)v.x * v.x + (double)v.y * v.y +
             (double)v.z * v.z + (double)v.w * v.w;
      }
      sC2[tid] = (float)s;
    }
    __syncthreads();
    #pragma unroll 2
    for (int c = 0; c < 256; ++c) {
      const float4* cr = reinterpret_cast<const float4*>(sW + c * kCDim);
      // 16 small partial dots, then binary-tree combine (error ~2e-6)
      float p[16];
      #pragma unroll
      for (int j = 0; j < 16; ++j) {
        float4 cv = cr[j];   // warp-uniform -> broadcast, conflict-free
        float t = zf[j].x * cv.x;
        t = fmaf(zf[j].y, cv.y, t);
        t = fmaf(zf[j].z, cv.z, t);
        t = fmaf(zf[j].w, cv.w, t);
        p[j] = t;
      }
      #pragma unroll
      for (int s = 8; s >= 1; s >>= 1)
        #pragma unroll
        for (int j = 0; j < 16; ++j)
          if (j < s) p[j] = p[j] + p[j + s];
      const float dist = fmaf(-2.f, p[0], sC2[c]);
      const int g = pass * 256 + c;
      if (dist < best) { best = dist; bidx = g; }     // strict < == first-min
    }
  }

  // gather + straight-through; write z_q and indices
  {
    const float4* cr = reinterpret_cast<const float4*>(cbk + bidx * kCDim);
    const bool wZ = out_size >= 2LL * kB * kTD;
    float* ozq = out + (size_t)kB * kTD + (size_t)(b0 + row) * kTD + tok * kCDim;
    #pragma unroll
    for (int j = 0; j < 16; ++j) {
      float4 cv = __ldg(&cr[j]);
      float4 zq;
      zq.x = zf[j].x + (cv.x - zf[j].x);   // ST arithmetic exactly as reference
      zq.y = zf[j].y + (cv.y - zf[j].y);
      zq.z = zf[j].z + (cv.z - zf[j].z);
      zq.w = zf[j].w + (cv.w - zf[j].w);
      reinterpret_cast<float4*>(zp)[j] = zq;          // decoder input
      if (wZ) reinterpret_cast<float4*>(ozq)[j] = zq;
    }
    if (out_size >= 2LL * kB * kTD + (long long)kB * kTok)
      out[(size_t)2 * kB * kTD + (size_t)(b0 + row) * kTok + tok] = (float)bidx;
  }

  // ---------------- GEMM3: h2 = relu(z_q @ dec_w1 + b1) ----------------
  #pragma unroll
  for (int i = 0; i < 4; ++i)
    #pragma unroll
    for (int j = 0; j < 4; ++j) acc[i][j] = 0.f;

  for (int kt = 0; kt < 4; ++kt) {
    __syncthreads();
    const float4* src = reinterpret_cast<const float4*>(dw1 + kt * 128 * kHid);
    float4* dst = reinterpret_cast<float4*>(sW);
    #pragma unroll
    for (int i = 0; i < 8; ++i)
      dst[tid + i * kThreads] = src[tid + i * kThreads];
    __syncthreads();
    gemm128(sZ + kt * 128, kTD, sW, r0, c0, acc);
  }
  #pragma unroll
  for (int i = 0; i < 4; ++i)
    #pragma unroll
    for (int j = 0; j < 4; ++j) {
      float v = acc[i][j] + __ldg(&db1[c0 + j]);
      sH[(r0 + i) * kHid + c0 + j] = fmaxf(v, 0.f);
    }

  // ---------------- GEMM4: recon = h2 @ dec_w2 + b2 -> gmem ----------------
  for (int nc = 0; nc < 4; ++nc) {
    const int n0 = nc * 128;
    __syncthreads();
    #pragma unroll
    for (int q = tid; q < 4096; q += kThreads) {
      const int k = q >> 5, j4 = q & 31;
      reinterpret_cast<float4*>(sW)[q] =
          *reinterpret_cast<const float4*>(dw2 + k * kTD + n0 + j4 * 4);
    }
    __syncthreads();
    #pragma unroll
    for (int i = 0; i < 4; ++i)
      #pragma unroll
      for (int j = 0; j < 4; ++j) acc[i][j] = 0.f;
    gemm128(sH, kHid, sW, r0, c0, acc);
    #pragma unroll
    for (int i = 0; i < 4; ++i) {
      float4 o;
      o.x = acc[i][0] + __ldg(&db2[n0 + c0 + 0]);
      o.y = acc[i][1] + __ldg(&db2[n0 + c0 + 1]);
      o.z = acc[i][2] + __ldg(&db2[n0 + c0 + 2]);
      o.w = acc[i][3] + __ldg(&db2[n0 + c0 + 3]);
      *reinterpret_cast<float4*>(out + (size_t)(b0 + r0 + i) * kTD + n0 + c0) = o;
    }
  }
}

extern "C" void kernel_launch(void* const* d_in, const int* in_sizes, int n_in,
                              void* d_out, int out_size)
{
  const float* x   = (const float*)d_in[0];
  const float* ew1 = (const float*)d_in[1];
  const float* eb1 = (const float*)d_in[2];
  const float* ew2 = (const float*)d_in[3];
  const float* eb2 = (const float*)d_in[4];
  const float* cbk = (const float*)d_in[5];
  const float* dw1 = (const float*)d_in[6];
  const float* db1 = (const float*)d_in[7];
  const float* dw2 = (const float*)d_in[8];
  const float* db2 = (const float*)d_in[9];

  cudaFuncSetAttribute(vqvae_fused,
                       cudaFuncAttributeMaxDynamicSharedMemorySize, kSmemBytes);
  vqvae_fused<<<kB / kM, kThreads, kSmemBytes>>>(
      x, ew1, eb1, ew2, eb2, cbk, dw1, db1, dw2, db2,
      (float*)d_out, (long long)out_size);
}

// round 7
// speedup vs baseline: 1.0008x; 1.0008x over previous
#include <cuda_runtime.h>

// VQ-VAE time-series forward, fully fused, fp32.
// B=16384, T*D=512, HID=128, N_TOKENS=8, CODE_DIM=64, N_CODES=512.
// One CTA processes M=64 batch rows end-to-end.
// R2: fp64-accumulated c2 + tree-summed dot for the VQ argmin (kills the
//     near-tie flip seen in R1); z2 dropped (constant across codes).

namespace {
constexpr int kB       = 16384;
constexpr int kM       = 64;
constexpr int kThreads = 512;
constexpr int kTD      = 512;   // T*D == N_TOKENS*CODE_DIM
constexpr int kHid     = 128;
constexpr int kCDim    = 64;
constexpr int kTok     = 8;
// smem: sZ[64][512] | sH[64][128] | sW[128][128] | sC2[256]
constexpr int kSmemFloats = kM * kTD + kM * kHid + 128 * 128 + 256;   // 57600
constexpr int kSmemBytes  = kSmemFloats * 4;                          // 230400 <= 232448
}

// C[64,128-chunk] += A[64,128] * B[128,128], 4x4 register micro-tile.
// r0 = (tid>>5)*4  (warp-uniform -> A loads broadcast), c0 = (tid&31)*4.
__device__ __forceinline__ void gemm128(const float* __restrict__ sA, int lda,
                                        const float* __restrict__ sB,
                                        int r0, int c0, float (&acc)[4][4])
{
  #pragma unroll 4
  for (int kk = 0; kk < 128; kk += 4) {
    float4 av[4], bv[4];
    #pragma unroll
    for (int i = 0; i < 4; ++i)
      av[i] = *reinterpret_cast<const float4*>(sA + (r0 + i) * lda + kk);
    #pragma unroll
    for (int j = 0; j < 4; ++j)
      bv[j] = *reinterpret_cast<const float4*>(sB + (kk + j) * 128 + c0);
    #pragma unroll
    for (int i = 0; i < 4; ++i) {
      acc[i][0] = fmaf(av[i].x, bv[0].x, acc[i][0]);
      acc[i][1] = fmaf(av[i].x, bv[0].y, acc[i][1]);
      acc[i][2] = fmaf(av[i].x, bv[0].z, acc[i][2]);
      acc[i][3] = fmaf(av[i].x, bv[0].w, acc[i][3]);
      acc[i][0] = fmaf(av[i].y, bv[1].x, acc[i][0]);
      acc[i][1] = fmaf(av[i].y, bv[1].y, acc[i][1]);
      acc[i][2] = fmaf(av[i].y, bv[1].z, acc[i][2]);
      acc[i][3] = fmaf(av[i].y, bv[1].w, acc[i][3]);
      acc[i][0] = fmaf(av[i].z, bv[2].x, acc[i][0]);
      acc[i][1] = fmaf(av[i].z, bv[2].y, acc[i][1]);
      acc[i][2] = fmaf(av[i].z, bv[2].z, acc[i][2]);
      acc[i][3] = fmaf(av[i].z, bv[2].w, acc[i][3]);
      acc[i][0] = fmaf(av[i].w, bv[3].x, acc[i][0]);
      acc[i][1] = fmaf(av[i].w, bv[3].y, acc[i][1]);
      acc[i][2] = fmaf(av[i].w, bv[3].z, acc[i][2]);
      acc[i][3] = fmaf(av[i].w, bv[3].w, acc[i][3]);
    }
  }
}

__global__ void __launch_bounds__(kThreads, 1)
vqvae_fused(const float* __restrict__ x,
            const float* __restrict__ ew1, const float* __restrict__ eb1,
            const float* __restrict__ ew2, const float* __restrict__ eb2,
            const float* __restrict__ cbk,
            const float* __restrict__ dw1, const float* __restrict__ db1,
            const float* __restrict__ dw2, const float* __restrict__ db2,
            float* __restrict__ out, long long out_size)
{
  extern __shared__ float smem[];
  float* sZ  = smem;                    // [64][512] x tile, then z_e, then z_q
  float* sH  = sZ + kM * kTD;           // [64][128]
  float* sW  = sH + kM * kHid;          // [128][128] weight / codebook tile
  float* sC2 = sW + 128 * 128;          // [256] per-code ||c||^2 (fp64-accumulated)

  const int tid = threadIdx.x;
  const int b0  = blockIdx.x * kM;
  const int r0  = (tid >> 5) * 4;       // warp-uniform row group
  const int c0  = (tid & 31) * 4;       // per-lane col group

  // ---------------- load X tile [64,512] into sZ ----------------
  {
    const float4* src = reinterpret_cast<const float4*>(x + (size_t)b0 * kTD);
    float4* dst = reinterpret_cast<float4*>(sZ);
    #pragma unroll
    for (int i = 0; i < 16; ++i)
      dst[tid + i * kThreads] = src[tid + i * kThreads];
  }

  float acc[4][4];

  // ---------------- GEMM1: h = relu(X @ enc_w1 + b1) ----------------
  #pragma unroll
  for (int i = 0; i < 4; ++i)
    #pragma unroll
    for (int j = 0; j < 4; ++j) acc[i][j] = 0.f;

  for (int kt = 0; kt < 4; ++kt) {
    __syncthreads();
    const float4* src = reinterpret_cast<const float4*>(ew1 + kt * 128 * kHid);
    float4* dst = reinterpret_cast<float4*>(sW);
    #pragma unroll
    for (int i = 0; i < 8; ++i)
      dst[tid + i * kThreads] = src[tid + i * kThreads];
    __syncthreads();
    gemm128(sZ + kt * 128, kTD, sW, r0, c0, acc);
  }
  #pragma unroll
  for (int i = 0; i < 4; ++i)
    #pragma unroll
    for (int j = 0; j < 4; ++j) {
      float v = acc[i][j] + __ldg(&eb1[c0 + j]);
      sH[(r0 + i) * kHid + c0 + j] = fmaxf(v, 0.f);
    }

  // ---------------- GEMM2: z_e = h @ enc_w2 + b2 (4 N-chunks of 128) ----------------
  for (int nc = 0; nc < 4; ++nc) {
    const int n0 = nc * 128;
    __syncthreads();
    #pragma unroll
    for (int q = tid; q < 4096; q += kThreads) {   // float4 units of the tile
      const int k = q >> 5, j4 = q & 31;
      reinterpret_cast<float4*>(sW)[q] =
          *reinterpret_cast<const float4*>(ew2 + k * kTD + n0 + j4 * 4);
    }
    __syncthreads();
    #pragma unroll
    for (int i = 0; i < 4; ++i)
      #pragma unroll
      for (int j = 0; j < 4; ++j) acc[i][j] = 0.f;
    gemm128(sH, kHid, sW, r0, c0, acc);
    #pragma unroll
    for (int i = 0; i < 4; ++i)
      #pragma unroll
      for (int j = 0; j < 4; ++j)
        sZ[(r0 + i) * kTD + n0 + c0 + j] = acc[i][j] + __ldg(&eb2[n0 + c0 + j]);
  }
  __syncthreads();

  // ---------------- LayerNorm + VQ: one token-instance per thread ----------------
  const int row = tid >> 3;
  const int tok = tid & 7;
  float* zp = sZ + row * kTD + tok * kCDim;

  float4 zf[16];
  float mu = 0.f;
  #pragma unroll
  for (int j = 0; j < 16; ++j) {
    zf[j] = reinterpret_cast<const float4*>(zp)[j];
    mu += (zf[j].x + zf[j].y) + (zf[j].z + zf[j].w);
  }
  mu *= (1.f / 64.f);
  float var = 0.f;
  #pragma unroll
  for (int j = 0; j < 16; ++j) {
    float dx = zf[j].x - mu, dy = zf[j].y - mu, dz = zf[j].z - mu, dw = zf[j].w - mu;
    var += (dx * dx + dy * dy) + (dz * dz + dw * dw);
  }
  var *= (1.f / 64.f);
  const float rs = rsqrtf(var + 1e-5f);
  #pragma unroll
  for (int j = 0; j < 16; ++j) {
    zf[j].x = (zf[j].x - mu) * rs;
    zf[j].y = (zf[j].y - mu) * rs;
    zf[j].z = (zf[j].z - mu) * rs;
    zf[j].w = (zf[j].w - mu) * rs;
  }

  // argmin over codes of  c2[k] - 2*dot[k]   (z2 is constant -> dropped)
  float best = 3.402823466e38f;
  int bidx = 0;
  for (int pass = 0; pass < 2; ++pass) {
    __syncthreads();
    {  // codebook tile: 256 codes x 64 -> sW (contiguous 64KB)
      const float4* src = reinterpret_cast<const float4*>(cbk + pass * 256 * kCDim);
      float4* dst = reinterpret_cast<float4*>(sW);
      #pragma unroll
      for (int i = 0; i < 8; ++i)
        dst[tid + i * kThreads] = src[tid + i * kThreads];
    }
    __syncthreads();
    if (tid < 256) {
      // fp64-accumulated ||c||^2: error ~ ulp(64)/2 ~= 4e-6 instead of ~2e-5
      double s = 0.0;
      const float4* cr = reinterpret_cast<const float4*>(sW + tid * kCDim);
      #pragma unroll
      for (int j = 0; j < 16; ++j) {
        float4 v = cr[j];
        s += (double)v.x * v.x + (double)v.y * v.y +
             (double)v.z * v.z + (double)v.w * v.w;
      }
      sC2[tid] = (float)s;
    }
    __syncthreads();
    #pragma unroll 2
    for (int c = 0; c < 256; ++c) {
      const float4* cr = reinterpret_cast<const float4*>(sW + c * kCDim);
      // 16 small partial dots, then binary-tree combine (error ~2e-6)
      float p[16];
      #pragma unroll
      for (int j = 0; j < 16; ++j) {
        float4 cv = cr[j];   // warp-uniform -> broadcast, conflict-free
        float t = zf[j].x * cv.x;
        t = fmaf(zf[j].y, cv.y, t);
        t = fmaf(zf[j].z, cv.z, t);
        t = fmaf(zf[j].w, cv.w, t);
        p[j] = t;
      }
      #pragma unroll
      for (int s = 8; s >= 1; s >>= 1)
        #pragma unroll
        for (int j = 0; j < 16; ++j)
          if (j < s) p[j] = p[j] + p[j + s];
      const float dist = fmaf(-2.f, p[0], sC2[c]);
      const int g = pass * 256 + c;
      if (dist < best) { best = dist; bidx = g; }     // strict < == first-min
    }
  }

  // gather + straight-through; write z_q and indices
  {
    const float4* cr = reinterpret_cast<const float4*>(cbk + bidx * kCDim);
    const bool wZ = out_size >= 2LL * kB * kTD;
    float* ozq = out + (size_t)kB * kTD + (size_t)(b0 + row) * kTD + tok * kCDim;
    #pragma unroll
    for (int j = 0; j < 16; ++j) {
      float4 cv = __ldg(&cr[j]);
      float4 zq;
      zq.x = zf[j].x + (cv.x - zf[j].x);   // ST arithmetic exactly as reference
      zq.y = zf[j].y + (cv.y - zf[j].y);
      zq.z = zf[j].z + (cv.z - zf[j].z);
      zq.w = zf[j].w + (cv.w - zf[j].w);
      reinterpret_cast<float4*>(zp)[j] = zq;          // decoder input
      if (wZ) reinterpret_cast<float4*>(ozq)[j] = zq;
    }
    if (out_size >= 2LL * kB * kTD + (long long)kB * kTok)
      out[(size_t)2 * kB * kTD + (size_t)(b0 + row) * kTok + tok] = (float)bidx;
  }

  // ---------------- GEMM3: h2 = relu(z_q @ dec_w1 + b1) ----------------
  #pragma unroll
  for (int i = 0; i < 4; ++i)
    #pragma unroll
    for (int j = 0; j < 4; ++j) acc[i][j] = 0.f;

  for (int kt = 0; kt < 4; ++kt) {
    __syncthreads();
    const float4* src = reinterpret_cast<const float4*>(dw1 + kt * 128 * kHid);
    float4* dst = reinterpret_cast<float4*>(sW);
    #pragma unroll
    for (int i = 0; i < 8; ++i)
      dst[tid + i * kThreads] = src[tid + i * kThreads];
    __syncthreads();
    gemm128(sZ + kt * 128, kTD, sW, r0, c0, acc);
  }
  #pragma unroll
  for (int i = 0; i < 4; ++i)
    #pragma unroll
    for (int j = 0; j < 4; ++j) {
      float v = acc[i][j] + __ldg(&db1[c0 + j]);
      sH[(r0 + i) * kHid + c0 + j] = fmaxf(v, 0.f);
    }

  // ---------------- GEMM4: recon = h2 @ dec_w2 + b2 -> gmem ----------------
  for (int nc = 0; nc < 4; ++nc) {
    const int n0 = nc * 128;
    __syncthreads();
    #pragma unroll
    for (int q = tid; q < 4096; q += kThreads) {
      const int k = q >> 5, j4 = q & 31;
      reinterpret_cast<float4*>(sW)[q] =
          *reinterpret_cast<const float4*>(dw2 + k * kTD + n0 + j4 * 4);
    }
    __syncthreads();
    #pragma unroll
    for (int i = 0; i < 4; ++i)
      #pragma unroll
      for (int j = 0; j < 4; ++j) acc[i][j] = 0.f;
    gemm128(sH, kHid, sW, r0, c0, acc);
    #pragma unroll
    for (int i = 0; i < 4; ++i) {
      float4 o;
      o.x = acc[i][0] + __ldg(&db2[n0 + c0 + 0]);
      o.y = acc[i][1] + __ldg(&db2[n0 + c0 + 1]);
      o.z = acc[i][2] + __ldg(&db2[n0 + c0 + 2]);
      o.w = acc[i][3] + __ldg(&db2[n0 + c0 + 3]);
      *reinterpret_cast<float4*>(out + (size_t)(b0 + r0 + i) * kTD + n0 + c0) = o;
    }
  }
}

extern "C" void kernel_launch(void* const* d_in, const int* in_sizes, int n_in,
                              void* d_out, int out_size)
{
  const float* x   = (const float*)d_in[0];
  const float* ew1 = (const float*)d_in[1];
  const float* eb1 = (const float*)d_in[2];
  const float* ew2 = (const float*)d_in[3];
  const float* eb2 = (const float*)d_in[4];
  const float* cbk = (const float*)d_in[5];
  const float* dw1 = (const float*)d_in[6];
  const float* db1 = (const float*)d_in[7];
  const float* dw2 = (const float*)d_in[8];
  const float* db2 = (const float*)d_in[9];

  cudaFuncSetAttribute(vqvae_fused,
                       cudaFuncAttributeMaxDynamicSharedMemorySize, kSmemBytes);
  vqvae_fused<<<kB / kM, kThreads, kSmemBytes>>>(
      x, ew1, eb1, ew2, eb2, cbk, dw1, db1, dw2, db2,
      (float*)d_out, (long long)out_size);
}